// round 5
// baseline (speedup 1.0000x reference)
#include <cuda_runtime.h>
#include <math.h>

#define NMAX 4096
#define FMAX 1024
#define IMGF 256.0f
#define NPIX 65536
#define INV_SIGMA (1.0f / 3e-05f)

// Scratch (no allocations allowed in kernel_launch)
__device__ float2 g_v2d[NMAX];
__device__ float4 g_f0[FMAX];   // A0,B0,C0,A1
__device__ float4 g_f1[FMAX];   // B1,C1,A2,B2
__device__ float  g_f2[FMAX];   // C2
__device__ float  g_partial[256];

// ---------------- Kernel 1: project vertices ----------------
__global__ void project_kernel(const float* __restrict__ verts,
                               const float* __restrict__ K,
                               const float* __restrict__ R,
                               const float* __restrict__ t,
                               int N) {
    int i = blockIdx.x * blockDim.x + threadIdx.x;
    if (i >= N) return;
    float vx = verts[3 * i + 0];
    float vy = verts[3 * i + 1];
    float vz = verts[3 * i + 2];
    // v = vertices @ R^T + t   (v_j = sum_k vert_k * R[j,k])
    float p0 = R[0] * vx + R[1] * vy + R[2] * vz + t[0];
    float p1 = R[3] * vx + R[4] * vy + R[5] * vz + t[1];
    float p2 = R[6] * vx + R[7] * vy + R[8] * vz + t[2];
    float zd = p2 + 1e-5f;
    float xn = p0 / zd;
    float yn = p1 / zd;
    // uv = [xn,yn,1] @ K^T
    float u  = K[0] * xn + K[1] * yn + K[2];
    float vv = K[3] * xn + K[4] * yn + K[5];
    vv = IMGF - vv;
    u  = 2.0f * (u  - IMGF * 0.5f) / IMGF;
    vv = 2.0f * (vv - IMGF * 0.5f) / IMGF;
    g_v2d[i] = make_float2(u, vv);
}

// ---------------- Kernel 2: per-face edge coefficients ----------------
// w_e(px,py) = A_e*px + B_e*py + C_e  (sign s folded in)
__global__ void faceprep_kernel(const int* __restrict__ faces, int F) {
    int f = blockIdx.x * blockDim.x + threadIdx.x;
    if (f >= F) return;
    int i0 = faces[3 * f + 0];
    int i1 = faces[3 * f + 1];
    int i2 = faces[3 * f + 2];
    float2 v0 = g_v2d[i0];
    float2 v1 = g_v2d[i1];
    float2 v2 = g_v2d[i2];
    float x0 = v0.x, y0 = v0.y;
    float x1 = v1.x, y1 = v1.y;
    float x2 = v2.x, y2 = v2.y;

    float area = (x1 - x0) * (y2 - y0) - (y1 - y0) * (x2 - x0);
    float s = (area > 0.0f) ? 1.0f : ((area < 0.0f) ? -1.0f : 0.0f);

    // edge 0: verts 0 -> 1
    float dx01 = x1 - x0, dy01 = y1 - y0;
    float A0 = -s * dy01;
    float B0 =  s * dx01;
    float C0 =  s * (dy01 * x0 - dx01 * y0);
    // edge 1: verts 1 -> 2
    float dx12 = x2 - x1, dy12 = y2 - y1;
    float A1 = -s * dy12;
    float B1 =  s * dx12;
    float C1 =  s * (dy12 * x1 - dx12 * y1);
    // edge 2: verts 2 -> 0
    float dx20 = x0 - x2, dy20 = y0 - y2;
    float A2 = -s * dy20;
    float B2 =  s * dx20;
    float C2 =  s * (dy20 * x2 - dx20 * y2);

    g_f0[f] = make_float4(A0, B0, C0, A1);
    g_f1[f] = make_float4(B1, C1, A2, B2);
    g_f2[f] = C2;
}

// ---------------- Kernel 3: rasterize + per-block partial loss ----------------
__global__ void __launch_bounds__(256) raster_kernel(const float* __restrict__ image_ref, int F) {
    __shared__ float4 s0[FMAX];
    __shared__ float4 s1[FMAX];
    __shared__ float  s2[FMAX];
    __shared__ float  red[256];

    for (int i = threadIdx.x; i < F; i += blockDim.x) {
        s0[i] = g_f0[i];
        s1[i] = g_f1[i];
        s2[i] = g_f2[i];
    }
    __syncthreads();

    int pix = blockIdx.x * blockDim.x + threadIdx.x;   // 256 blocks x 256 thr = 65536
    int row = pix >> 8;
    int col = pix & 255;
    // px varies fastest (tile), py = -ii repeated
    float px =  (2.0f * (float)col + 1.0f - IMGF) * (1.0f / IMGF);
    float py = -((2.0f * (float)row + 1.0f - IMGF) * (1.0f / IMGF));

    float acc = 0.0f;
    bool covered = false;

    for (int f = 0; f < F; ++f) {
        if (!covered) {
            float4 a = s0[f];
            float4 b = s1[f];
            float  c2 = s2[f];
            float w0 = fmaf(a.x, px, fmaf(a.y, py, a.z));
            float w1 = fmaf(a.w, px, fmaf(b.x, py, b.y));
            float w2 = fmaf(b.z, px, fmaf(b.w, py, c2));
            float d  = fminf(w0, fminf(w1, w2));
            float tt = d * INV_SIGMA;
            if (tt > 17.4f) {
                // sigmoid rounds to exactly 1.0f in fp32 -> log1p(-1+1e-12) = -inf
                // -> cov = 1 regardless of all other faces.
                covered = true;
            } else if (tt > -30.0f) {
                // soft band: full-precision path (rare)
                float prob = 1.0f / (1.0f + expf(-tt));
                acc += log1pf(1e-12f - prob);
            }
            // tt <= -30: contribution < 1e-13 per face, negligible
        }
        if (__all_sync(0xffffffffu, covered)) break;
    }

    float cov = covered ? 1.0f : (1.0f - expf(acc));
    float df = cov - image_ref[pix];
    red[threadIdx.x] = df * df;
    __syncthreads();
    #pragma unroll
    for (int s = 128; s > 0; s >>= 1) {
        if (threadIdx.x < s) red[threadIdx.x] += red[threadIdx.x + s];
        __syncthreads();
    }
    if (threadIdx.x == 0) g_partial[blockIdx.x] = red[0];
}

// ---------------- Kernel 4: deterministic final reduction ----------------
__global__ void finalreduce_kernel(float* __restrict__ out) {
    __shared__ float red[256];
    red[threadIdx.x] = g_partial[threadIdx.x];
    __syncthreads();
    #pragma unroll
    for (int s = 128; s > 0; s >>= 1) {
        if (threadIdx.x < s) red[threadIdx.x] += red[threadIdx.x + s];
        __syncthreads();
    }
    if (threadIdx.x == 0) out[0] = red[0];
}

extern "C" void kernel_launch(void* const* d_in, const int* in_sizes, int n_in,
                              void* d_out, int out_size) {
    const float* verts     = (const float*)d_in[0];  // (1,N,3)
    const float* K         = (const float*)d_in[1];  // (1,3,3)
    const float* R         = (const float*)d_in[2];  // (1,3,3)
    const float* t         = (const float*)d_in[3];  // (1,3)
    const float* image_ref = (const float*)d_in[4];  // (256,256)
    const int*   faces     = (const int*)d_in[5];    // (1,F,3)
    float* out = (float*)d_out;

    int N = in_sizes[0] / 3;
    int F = in_sizes[5] / 3;
    if (N > NMAX) N = NMAX;
    if (F > FMAX) F = FMAX;

    project_kernel<<<(N + 255) / 256, 256>>>(verts, K, R, t, N);
    faceprep_kernel<<<(F + 255) / 256, 256>>>(faces, F);
    raster_kernel<<<256, 256>>>(image_ref, F);
    finalreduce_kernel<<<1, 256>>>(out);
}

// round 6
// speedup vs baseline: 7.4535x; 7.4535x over previous
#include <cuda_runtime.h>
#include <math.h>

#define NMAX 4096
#define FMAX 1024
#define IMGF 256.0f
#define INV_SIGMA (1.0f / 3e-05f)

// Scratch (no allocations allowed in kernel_launch)
__device__ float4 g_f0[FMAX];   // A0,B0,C0,A1
__device__ float4 g_f1[FMAX];   // B1,C1,A2,B2
__device__ float  g_f2[FMAX];   // C2
__device__ float  g_partial[256];
__device__ unsigned g_ticket = 0;

// ---------------- Kernel 1: project vertices + face edge coefficients ----------------
__global__ void __launch_bounds__(512) prep_kernel(const float* __restrict__ verts,
                                                   const float* __restrict__ K,
                                                   const float* __restrict__ R,
                                                   const float* __restrict__ t,
                                                   const int* __restrict__ faces,
                                                   int N, int F) {
    __shared__ float2 v2d[NMAX];

    float R0 = R[0], R1 = R[1], R2 = R[2];
    float R3 = R[3], R4 = R[4], R5 = R[5];
    float R6 = R[6], R7 = R[7], R8 = R[8];
    float t0 = t[0], t1 = t[1], t2 = t[2];
    float K0 = K[0], K1 = K[1], K2 = K[2];
    float K3 = K[3], K4 = K[4], K5 = K[5];

    for (int i = threadIdx.x; i < N; i += blockDim.x) {
        float vx = verts[3 * i + 0];
        float vy = verts[3 * i + 1];
        float vz = verts[3 * i + 2];
        float p0 = R0 * vx + R1 * vy + R2 * vz + t0;
        float p1 = R3 * vx + R4 * vy + R5 * vz + t1;
        float p2 = R6 * vx + R7 * vy + R8 * vz + t2;
        float zd = p2 + 1e-5f;
        float xn = p0 / zd;
        float yn = p1 / zd;
        float u  = K0 * xn + K1 * yn + K2;
        float vv = K3 * xn + K4 * yn + K5;
        vv = IMGF - vv;
        u  = 2.0f * (u  - IMGF * 0.5f) / IMGF;
        vv = 2.0f * (vv - IMGF * 0.5f) / IMGF;
        v2d[i] = make_float2(u, vv);
    }
    __syncthreads();

    for (int f = threadIdx.x; f < F; f += blockDim.x) {
        int i0 = faces[3 * f + 0];
        int i1 = faces[3 * f + 1];
        int i2 = faces[3 * f + 2];
        float2 v0 = v2d[i0];
        float2 v1 = v2d[i1];
        float2 v2 = v2d[i2];
        float x0 = v0.x, y0 = v0.y;
        float x1 = v1.x, y1 = v1.y;
        float x2 = v2.x, y2 = v2.y;

        float area = (x1 - x0) * (y2 - y0) - (y1 - y0) * (x2 - x0);
        float s = (area > 0.0f) ? 1.0f : ((area < 0.0f) ? -1.0f : 0.0f);

        float dx01 = x1 - x0, dy01 = y1 - y0;
        float A0 = -s * dy01;
        float B0 =  s * dx01;
        float C0 =  s * (dy01 * x0 - dx01 * y0);
        float dx12 = x2 - x1, dy12 = y2 - y1;
        float A1 = -s * dy12;
        float B1 =  s * dx12;
        float C1 =  s * (dy12 * x1 - dx12 * y1);
        float dx20 = x0 - x2, dy20 = y0 - y2;
        float A2 = -s * dy20;
        float B2 =  s * dx20;
        float C2 =  s * (dy20 * x2 - dx20 * y2);

        g_f0[f] = make_float4(A0, B0, C0, A1);
        g_f1[f] = make_float4(B1, C1, A2, B2);
        g_f2[f] = C2;
    }
    if (threadIdx.x == 0) g_ticket = 0;   // redundant with last-block reset; replay-safe
}

// ---------------- Kernel 2: tile-culled rasterize + full reduce ----------------
// 256 blocks = 16x16 tiles of 16x16 pixels. Per tile:
//   pass 1: classify all F faces -> (covers whole tile | irrelevant | interesting)
//   if any face covers whole tile: cov=1 for all pixels, skip per-pixel loop.
//   else: deterministic ballot+scan compaction of interesting faces into smem,
//         then per-pixel loop over the (small) compacted list.
__global__ void __launch_bounds__(256) raster_kernel(const float* __restrict__ image_ref,
                                                     int F, float* __restrict__ out) {
    __shared__ float4  c0[FMAX];
    __shared__ float4  c1[FMAX];
    __shared__ float   c2s[FMAX];
    __shared__ float    red[256];
    __shared__ unsigned gmask[32];
    __shared__ int      goff[32];
    __shared__ int      s_cnt;
    __shared__ int      s_allcov;
    __shared__ int      s_last;

    int tid = threadIdx.x;
    int tx = blockIdx.x & 15;
    int ty = blockIdx.x >> 4;
    int col = tx * 16 + (tid & 15);
    int row = ty * 16 + (tid >> 4);
    int pix = row * 256 + col;

    float px =  (2.0f * (float)col + 1.0f - IMGF) * (1.0f / IMGF);
    float py = -((2.0f * (float)row + 1.0f - IMGF) * (1.0f / IMGF));

    // tile center + half extent (pixel centers span +/- 15/256 around center)
    float cx =  (2.0f * (float)(tx * 16) + 16.0f - IMGF) * (1.0f / IMGF);
    float cy = -((2.0f * (float)(ty * 16) + 16.0f - IMGF) * (1.0f / IMGF));
    const float h = 15.0f / 256.0f;

    if (tid == 0) s_allcov = 0;
    __syncthreads();

    // ---- pass 1: classify (4 faces per thread, ballot per 32-face group) ----
    #pragma unroll
    for (int c = 0; c < 4; ++c) {
        int f = c * 256 + tid;
        bool interesting = false;
        if (f < F) {
            float4 a  = g_f0[f];
            float4 b  = g_f1[f];
            float  cc = g_f2[f];
            float w0 = fmaf(a.x, cx, fmaf(a.y, cy, a.z));
            float r0 = (fabsf(a.x) + fabsf(a.y)) * h;
            float w1 = fmaf(a.w, cx, fmaf(b.x, cy, b.y));
            float r1 = (fabsf(a.w) + fabsf(b.x)) * h;
            float w2 = fmaf(b.z, cx, fmaf(b.w, cy, cc));
            float r2 = (fabsf(b.z) + fabsf(b.w)) * h;
            float dmin = fminf(w0 - r0, fminf(w1 - r1, w2 - r2));
            float dmax = fminf(w0 + r0, fminf(w1 + r1, w2 + r2));
            if (dmin * INV_SIGMA > 18.0f) {
                s_allcov = 1;           // face fully covers the tile
            } else if (dmax * INV_SIGMA > -31.0f) {
                interesting = true;     // within band or partially covering
            }
        }
        unsigned m = __ballot_sync(0xffffffffu, interesting);
        if ((tid & 31) == 0) gmask[c * 8 + (tid >> 5)] = m;
    }
    __syncthreads();

    float cov;
    if (s_allcov) {
        cov = 1.0f;                     // whole tile covered: no per-pixel loop
    } else {
        // ---- deterministic exclusive scan of group popcounts (warp 0) ----
        if (tid < 32) {
            int cnt = __popc(gmask[tid]);
            int x = cnt;
            #pragma unroll
            for (int off = 1; off < 32; off <<= 1) {
                int y = __shfl_up_sync(0xffffffffu, x, off);
                if (tid >= off) x += y;
            }
            goff[tid] = x - cnt;
            if (tid == 31) s_cnt = x;
        }
        __syncthreads();

        // ---- compaction (fixed order: by face index) ----
        #pragma unroll
        for (int c = 0; c < 4; ++c) {
            int g = c * 8 + (tid >> 5);
            unsigned m = gmask[g];
            int lane = tid & 31;
            if (m & (1u << lane)) {
                int f = c * 256 + tid;
                int pos = goff[g] + __popc(m & ((1u << lane) - 1u));
                c0[pos]  = g_f0[f];
                c1[pos]  = g_f1[f];
                c2s[pos] = g_f2[f];
            }
        }
        __syncthreads();
        int cnt = s_cnt;

        // ---- per-pixel loop over compacted faces ----
        float acc = 0.0f;
        bool covered = false;
        for (int i = 0; i < cnt; ++i) {
            if (!covered) {
                float4 a  = c0[i];
                float4 b  = c1[i];
                float  cc = c2s[i];
                float w0 = fmaf(a.x, px, fmaf(a.y, py, a.z));
                float w1 = fmaf(a.w, px, fmaf(b.x, py, b.y));
                float w2 = fmaf(b.z, px, fmaf(b.w, py, cc));
                float d  = fminf(w0, fminf(w1, w2));
                float tt = d * INV_SIGMA;
                if (tt > 17.4f) {
                    covered = true;     // sigmoid == 1.0f in fp32 -> cov = 1
                } else if (tt > -30.0f) {
                    float prob = 1.0f / (1.0f + expf(-tt));
                    acc += log1pf(1e-12f - prob);
                }
            }
            if (__all_sync(0xffffffffu, covered)) break;
        }
        cov = covered ? 1.0f : (1.0f - expf(acc));
    }

    // ---- block reduction of squared error ----
    float df = cov - image_ref[pix];
    red[tid] = df * df;
    __syncthreads();
    #pragma unroll
    for (int s = 128; s > 0; s >>= 1) {
        if (tid < s) red[tid] += red[tid + s];
        __syncthreads();
    }
    if (tid == 0) {
        g_partial[blockIdx.x] = red[0];
        __threadfence();
        unsigned tkt = atomicAdd(&g_ticket, 1u);
        s_last = (tkt == gridDim.x - 1) ? 1 : 0;
    }
    __syncthreads();

    // ---- last block performs the deterministic final reduction ----
    if (s_last) {
        __threadfence();
        red[tid] = g_partial[tid];
        __syncthreads();
        #pragma unroll
        for (int s = 128; s > 0; s >>= 1) {
            if (tid < s) red[tid] += red[tid + s];
            __syncthreads();
        }
        if (tid == 0) {
            out[0] = red[0];
            g_ticket = 0;               // reset for next graph replay
        }
    }
}

extern "C" void kernel_launch(void* const* d_in, const int* in_sizes, int n_in,
                              void* d_out, int out_size) {
    const float* verts     = (const float*)d_in[0];  // (1,N,3)
    const float* K         = (const float*)d_in[1];  // (1,3,3)
    const float* R         = (const float*)d_in[2];  // (1,3,3)
    const float* t         = (const float*)d_in[3];  // (1,3)
    const float* image_ref = (const float*)d_in[4];  // (256,256)
    const int*   faces     = (const int*)d_in[5];    // (1,F,3)
    float* out = (float*)d_out;

    int N = in_sizes[0] / 3;
    int F = in_sizes[5] / 3;
    if (N > NMAX) N = NMAX;
    if (F > FMAX) F = FMAX;

    prep_kernel<<<1, 512>>>(verts, K, R, t, faces, N, F);
    raster_kernel<<<256, 256>>>(image_ref, F, out);
}